// round 8
// baseline (speedup 1.0000x reference)
#include <cuda_runtime.h>
#include <cstdint>

// Problem constants
#define TOTAL_N 341
#define BATCH   64
#define DMODEL  768
#define NHEADS  12
#define HDIM    64
#define MTOK    (BATCH * TOTAL_N)   // 21824

// Scratch (device globals: allocation-free)
__device__ __align__(1024) float g_qkv [(size_t)MTOK * 3 * DMODEL];   // [M, 2304] natural
__device__ __align__(1024) float g_att [(size_t)MTOK * DMODEL];       // [M, 768]  K-pair-permuted
__device__ __align__(1024) float g_xr  [(size_t)MTOK * DMODEL];       // rounded+permuted x
__device__ __align__(1024) float g_wqkv[(size_t)3 * DMODEL * DMODEL]; // rounded+permuted qkv_w
__device__ __align__(1024) float g_wproj[(size_t)DMODEL * DMODEL];    // rounded+permuted proj_w

// ---------------------------------------------------------------------------
// helpers
// ---------------------------------------------------------------------------
__device__ __forceinline__ float to_tf32(float x) {
    uint32_t y;
    asm("cvt.rna.tf32.f32 %0, %1;" : "=r"(y) : "f"(x));
    return __uint_as_float(y);
}

__device__ __forceinline__ uint32_t fau(float x) { return __float_as_uint(x); }

__device__ __forceinline__ void mma_tf32(float* c, const uint32_t* a, uint32_t b0, uint32_t b1) {
    asm volatile(
        "mma.sync.aligned.m16n8k8.row.col.f32.tf32.tf32.f32 "
        "{%0,%1,%2,%3}, {%4,%5,%6,%7}, {%8,%9}, {%0,%1,%2,%3};\n"
        : "+f"(c[0]), "+f"(c[1]), "+f"(c[2]), "+f"(c[3])
        : "r"(a[0]), "r"(a[1]), "r"(a[2]), "r"(a[3]), "r"(b0), "r"(b1));
}

__device__ __forceinline__ int limit_of(int q) {
    if (q == 0)  return 341;
    if (q < 5)   return 5;
    if (q < 21)  return 21;
    if (q < 85)  return 85;
    return 341;
}

__device__ __forceinline__ void cp16(uint32_t dst, const float* src, int sz) {
    asm volatile("cp.async.cg.shared.global [%0], [%1], 16, %2;\n"
                 :: "r"(dst), "l"(src), "r"(sz));
}

__device__ __forceinline__ uint32_t smem_u32(const void* p) {
    return (uint32_t)__cvta_generic_to_shared(p);
}

// ---------------------------------------------------------------------------
// RNA round + K-pair permutation: within each 8-float K group,
// out[0]=in0 out[1]=in4 out[2]=in1 out[3]=in5 out[4]=in2 out[5]=in6 out[6]=in3 out[7]=in7
// so natural cols (t, t+4) become adjacent pair at position 2t.
// ---------------------------------------------------------------------------
__global__ __launch_bounds__(256) void round_perm_kernel(const float* __restrict__ s,
                                                         float* __restrict__ d, int n) {
    int i = (blockIdx.x * blockDim.x + threadIdx.x) * 8;
    if (i < n) {
        float4 a = *(const float4*)(s + i);
        float4 b = *(const float4*)(s + i + 4);
        float4 o0 = make_float4(to_tf32(a.x), to_tf32(b.x), to_tf32(a.y), to_tf32(b.y));
        float4 o1 = make_float4(to_tf32(a.z), to_tf32(b.z), to_tf32(a.w), to_tf32(b.w));
        *(float4*)(d + i)     = o0;
        *(float4*)(d + i + 4) = o1;
    }
}

// ---------------------------------------------------------------------------
// mma.sync tf32 GEMM v3: C[M,NG] = A[M,768] @ W[NG,768]^T + bias[NG]
// A and W are K-pair-permuted. CTA 128x256x32, warp tile 64x64, 8 warps.
// 3-stage cp.async pipeline, ONE barrier per k-iter, loads before compute.
// Fragment loads are LDS.64 (float2) thanks to the permutation.
// ---------------------------------------------------------------------------
#define TK     32
#define RS     36                                  // row stride in floats
#define A_ROWS 128
#define B_ROWS 256
#define STG_FL ((A_ROWS + B_ROWS) * RS)            // 13824 floats
#define STG_B  (STG_FL * 4)                        // 55296 bytes
#define NSTG   3
#define GEMM_SMEM (NSTG * STG_B)                   // 165888 bytes

template <int NG>
__global__ __launch_bounds__(256) void gemm_v3(const float* __restrict__ A,
                                               const float* __restrict__ W,
                                               const float* __restrict__ bias,
                                               float* __restrict__ C, int M) {
    extern __shared__ float sm[];

    const int tid  = threadIdx.x;
    const int lane = tid & 31;
    const int warp = tid >> 5;
    const int g    = lane >> 2;   // 0..7
    const int t    = lane & 3;    // 0..3
    const int wm   = warp >> 2;   // 0..1
    const int wn   = warp & 3;    // 0..3
    const int bm   = blockIdx.y * A_ROWS;
    const int bn   = blockIdx.x * B_ROWS;

    const uint32_t smb = smem_u32(sm);

    auto issue = [&](int kb, int s) {
        uint32_t base = smb + s * STG_B;
#pragma unroll
        for (int i = 0; i < 4; i++) {
            int idx = tid + i * 256;
            int row = idx >> 3, c = idx & 7;
            int gr = bm + row;
            int ok = gr < M;
            const float* src = A + (size_t)(ok ? gr : 0) * DMODEL + kb * TK + c * 4;
            cp16(base + (row * RS + c * 4) * 4, src, ok ? 16 : 0);
        }
        uint32_t bbase = base + A_ROWS * RS * 4;
#pragma unroll
        for (int i = 0; i < 8; i++) {
            int idx = tid + i * 256;
            int row = idx >> 3, c = idx & 7;
            const float* src = W + (size_t)(bn + row) * DMODEL + kb * TK + c * 4;
            cp16(bbase + (row * RS + c * 4) * 4, src, 16);
        }
    };

    float acc[4][8][4];
#pragma unroll
    for (int mi = 0; mi < 4; mi++)
#pragma unroll
        for (int ni = 0; ni < 8; ni++)
#pragma unroll
            for (int j = 0; j < 4; j++) acc[mi][ni][j] = 0.f;

    const int KT = DMODEL / TK;  // 24

    issue(0, 0);
    asm volatile("cp.async.commit_group;" ::: "memory");
    issue(1, 1);
    asm volatile("cp.async.commit_group;" ::: "memory");

    for (int kb = 0; kb < KT; kb++) {
        if (kb < KT - 1) asm volatile("cp.async.wait_group 1;" ::: "memory");
        else             asm volatile("cp.async.wait_group 0;" ::: "memory");
        __syncthreads();
        // Safe: stage (kb+2)%3 == (kb-1)%3 was fully consumed before this barrier.
        if (kb + 2 < KT) {
            issue(kb + 2, (kb + 2) % NSTG);
            asm volatile("cp.async.commit_group;" ::: "memory");
        }

        const int s = kb % NSTG;
        const float* As = sm + s * STG_FL;
        const float* Bs = As + A_ROWS * RS;

#pragma unroll
        for (int ks = 0; ks < 4; ks++) {
            const int k0 = ks * 8;
            uint32_t af[4][4];
#pragma unroll
            for (int mi = 0; mi < 4; mi++) {
                const float* pr = As + (wm * 64 + mi * 16 + g) * RS + k0 + 2 * t;
                float2 v0 = *(const float2*)pr;
                float2 v1 = *(const float2*)(pr + 8 * RS);
                af[mi][0] = fau(v0.x); af[mi][1] = fau(v1.x);
                af[mi][2] = fau(v0.y); af[mi][3] = fau(v1.y);
            }
#pragma unroll
            for (int ni = 0; ni < 8; ni++) {
                float2 vb = *(const float2*)(Bs + (wn * 64 + ni * 8 + g) * RS + k0 + 2 * t);
                uint32_t b0 = fau(vb.x);
                uint32_t b1 = fau(vb.y);
#pragma unroll
                for (int mi = 0; mi < 4; mi++) mma_tf32(acc[mi][ni], af[mi], b0, b1);
            }
        }
    }

    // epilogue: + bias, store (natural column layout)
#pragma unroll
    for (int mi = 0; mi < 4; mi++) {
        int r0 = bm + wm * 64 + mi * 16 + g;
        int r1 = r0 + 8;
#pragma unroll
        for (int ni = 0; ni < 8; ni++) {
            int col = bn + wn * 64 + ni * 8 + 2 * t;
            float b0 = bias[col], b1 = bias[col + 1];
            if (r0 < M) {
                float2 v = make_float2(acc[mi][ni][0] + b0, acc[mi][ni][1] + b1);
                *(float2*)(C + (size_t)r0 * NG + col) = v;
            }
            if (r1 < M) {
                float2 v = make_float2(acc[mi][ni][2] + b0, acc[mi][ni][3] + b1);
                *(float2*)(C + (size_t)r1 * NG + col) = v;
            }
        }
    }
}

// ---------------------------------------------------------------------------
// Fused flash attention. Output stores are K-pair-PERMUTED (consumed only by
// the proj GEMM as its A operand).
// ---------------------------------------------------------------------------
#define KS_STRIDE 68
#define VS_STRIDE 72

__global__ __launch_bounds__(128) void attn_kernel() {
    extern __shared__ float sm[];
    float* Ks = sm;
    float* Ps = sm + 64 * KS_STRIDE;
    float* Vs = sm + 2 * 64 * KS_STRIDE;

    const int tid  = threadIdx.x;
    const int lane = tid & 31;
    const int warp = tid >> 5;
    const int g    = lane >> 2;
    const int t    = lane & 3;

    const int q0 = blockIdx.x * 64;
    const int h  = blockIdx.y;
    const int b  = blockIdx.z;
    const size_t rowbase = (size_t)b * TOTAL_N;
    const int hoff = h * HDIM;

#pragma unroll
    for (int i = 0; i < 8; i++) {
        int idx = tid + i * 128;
        int row = idx >> 4;
        int c4  = (idx & 15) << 2;
        float4 v = make_float4(0.f, 0.f, 0.f, 0.f);
        int qi = q0 + row;
        if (qi < TOTAL_N) v = *(const float4*)(g_qkv + (rowbase + qi) * 2304 + hoff + c4);
        v.x = to_tf32(v.x); v.y = to_tf32(v.y); v.z = to_tf32(v.z); v.w = to_tf32(v.w);
        *(float4*)(Ps + row * KS_STRIDE + c4) = v;
    }
    __syncthreads();

    const int prow = warp * 16 + g;
    uint32_t qf[8][4];
#pragma unroll
    for (int d8 = 0; d8 < 8; d8++) {
        const float* p = Ps + prow * KS_STRIDE + d8 * 8 + t;
        qf[d8][0] = fau(p[0]);
        qf[d8][1] = fau(p[8 * KS_STRIDE]);
        qf[d8][2] = fau(p[4]);
        qf[d8][3] = fau(p[8 * KS_STRIDE + 4]);
    }
    __syncthreads();

    float o[8][4];
#pragma unroll
    for (int d8 = 0; d8 < 8; d8++)
#pragma unroll
        for (int j = 0; j < 4; j++) o[d8][j] = 0.f;

    float m0 = -1e30f, m1 = -1e30f, l0 = 0.f, l1 = 0.f;
    const int lim0 = limit_of(q0 + prow);
    const int lim1 = limit_of(q0 + prow + 8);

    for (int kt = 0; kt < 6; kt++) {
        int key0 = kt * 64;
#pragma unroll
        for (int i = 0; i < 8; i++) {
            int idx = tid + i * 128;
            int row = idx >> 4;
            int c4  = (idx & 15) << 2;
            float4 kv = make_float4(0.f, 0.f, 0.f, 0.f);
            float4 vv = make_float4(0.f, 0.f, 0.f, 0.f);
            int key = key0 + row;
            if (key < TOTAL_N) {
                const float* base = g_qkv + (rowbase + key) * 2304 + hoff;
                kv = *(const float4*)(base + DMODEL + c4);
                vv = *(const float4*)(base + 2 * DMODEL + c4);
            }
            kv.x = to_tf32(kv.x); kv.y = to_tf32(kv.y); kv.z = to_tf32(kv.z); kv.w = to_tf32(kv.w);
            vv.x = to_tf32(vv.x); vv.y = to_tf32(vv.y); vv.z = to_tf32(vv.z); vv.w = to_tf32(vv.w);
            *(float4*)(Ks + row * KS_STRIDE + c4) = kv;
            *(float4*)(Vs + row * VS_STRIDE + c4) = vv;
        }
        __syncthreads();

        float s[8][4];
#pragma unroll
        for (int ni = 0; ni < 8; ni++)
#pragma unroll
            for (int j = 0; j < 4; j++) s[ni][j] = 0.f;

#pragma unroll
        for (int d8 = 0; d8 < 8; d8++) {
#pragma unroll
            for (int ni = 0; ni < 8; ni++) {
                const float* p = Ks + (ni * 8 + g) * KS_STRIDE + d8 * 8 + t;
                mma_tf32(s[ni], qf[d8], fau(p[0]), fau(p[4]));
            }
        }

        float mx0 = -1e30f, mx1 = -1e30f;
#pragma unroll
        for (int ni = 0; ni < 8; ni++) {
            int col = key0 + ni * 8 + 2 * t;
            s[ni][0] = (col     < lim0) ? s[ni][0] * 0.125f : -1e30f;
            s[ni][1] = (col + 1 < lim0) ? s[ni][1] * 0.125f : -1e30f;
            s[ni][2] = (col     < lim1) ? s[ni][2] * 0.125f : -1e30f;
            s[ni][3] = (col + 1 < lim1) ? s[ni][3] * 0.125f : -1e30f;
            mx0 = fmaxf(mx0, fmaxf(s[ni][0], s[ni][1]));
            mx1 = fmaxf(mx1, fmaxf(s[ni][2], s[ni][3]));
        }
        mx0 = fmaxf(mx0, __shfl_xor_sync(0xffffffffu, mx0, 1));
        mx0 = fmaxf(mx0, __shfl_xor_sync(0xffffffffu, mx0, 2));
        mx1 = fmaxf(mx1, __shfl_xor_sync(0xffffffffu, mx1, 1));
        mx1 = fmaxf(mx1, __shfl_xor_sync(0xffffffffu, mx1, 2));

        float mn0 = fmaxf(m0, mx0);
        float mn1 = fmaxf(m1, mx1);
        float sc0 = __expf(m0 - mn0);
        float sc1 = __expf(m1 - mn1);
        m0 = mn0; m1 = mn1;

        float rs0 = 0.f, rs1 = 0.f;
#pragma unroll
        for (int ni = 0; ni < 8; ni++) {
            float p0 = __expf(s[ni][0] - mn0);
            float p1 = __expf(s[ni][1] - mn0);
            float p2 = __expf(s[ni][2] - mn1);
            float p3 = __expf(s[ni][3] - mn1);
            rs0 += p0 + p1;
            rs1 += p2 + p3;
            *(float2*)(Ps + prow * KS_STRIDE + ni * 8 + 2 * t) =
                make_float2(to_tf32(p0), to_tf32(p1));
            *(float2*)(Ps + (prow + 8) * KS_STRIDE + ni * 8 + 2 * t) =
                make_float2(to_tf32(p2), to_tf32(p3));
        }
        rs0 += __shfl_xor_sync(0xffffffffu, rs0, 1);
        rs0 += __shfl_xor_sync(0xffffffffu, rs0, 2);
        rs1 += __shfl_xor_sync(0xffffffffu, rs1, 1);
        rs1 += __shfl_xor_sync(0xffffffffu, rs1, 2);
        l0 = l0 * sc0 + rs0;
        l1 = l1 * sc1 + rs1;

#pragma unroll
        for (int d8 = 0; d8 < 8; d8++) {
            o[d8][0] *= sc0; o[d8][1] *= sc0;
            o[d8][2] *= sc1; o[d8][3] *= sc1;
        }
        __syncwarp();

#pragma unroll
        for (int kk = 0; kk < 8; kk++) {
            uint32_t af[4];
            const float* pp = Ps + prow * KS_STRIDE + kk * 8 + t;
            af[0] = fau(pp[0]);
            af[1] = fau(pp[8 * KS_STRIDE]);
            af[2] = fau(pp[4]);
            af[3] = fau(pp[8 * KS_STRIDE + 4]);
#pragma unroll
            for (int d8 = 0; d8 < 8; d8++) {
                const float* pv = Vs + (kk * 8 + t) * VS_STRIDE + d8 * 8 + g;
                mma_tf32(o[d8], af, fau(pv[0]), fau(pv[4 * VS_STRIDE]));
            }
        }
        __syncthreads();
    }

    // write O / l to g_att with K-pair permutation: natural col 2t -> pos,
    // natural col 2t+1 -> pos+2, where pos = 2*((2t)%4) + (2t)/4.
    float il0 = 1.f / l0;
    float il1 = 1.f / l1;
    int r0 = q0 + prow;
    int r1 = r0 + 8;
    const int posA = 2 * ((2 * t) & 3) + ((2 * t) >> 2);  // t:0->0, 1->4, 2->1, 3->5
#pragma unroll
    for (int d8 = 0; d8 < 8; d8++) {
        int base = hoff + d8 * 8;
        if (r0 < TOTAL_N) {
            float* p = g_att + (rowbase + r0) * DMODEL + base;
            p[posA]     = to_tf32(o[d8][0] * il0);
            p[posA + 2] = to_tf32(o[d8][1] * il0);
        }
        if (r1 < TOTAL_N) {
            float* p = g_att + (rowbase + r1) * DMODEL + base;
            p[posA]     = to_tf32(o[d8][2] * il1);
            p[posA + 2] = to_tf32(o[d8][3] * il1);
        }
    }
}

// ---------------------------------------------------------------------------
// launch
// ---------------------------------------------------------------------------
extern "C" void kernel_launch(void* const* d_in, const int* in_sizes, int n_in,
                              void* d_out, int out_size) {
    (void)in_sizes; (void)n_in; (void)out_size;
    const float* x      = (const float*)d_in[0];
    const float* qkv_w  = (const float*)d_in[1];
    const float* qkv_b  = (const float*)d_in[2];
    const float* proj_w = (const float*)d_in[3];
    const float* proj_b = (const float*)d_in[4];
    float* out = (float*)d_out;

    float *xr, *wq, *wp, *qkv, *att;
    cudaGetSymbolAddress((void**)&xr,  g_xr);
    cudaGetSymbolAddress((void**)&wq,  g_wqkv);
    cudaGetSymbolAddress((void**)&wp,  g_wproj);
    cudaGetSymbolAddress((void**)&qkv, g_qkv);
    cudaGetSymbolAddress((void**)&att, g_att);

    // RNA round + K-pair permute inputs consumed by the GEMMs
    {
        int n1 = MTOK * DMODEL;
        round_perm_kernel<<<(n1 / 8 + 255) / 256, 256>>>(x, xr, n1);
        int n2 = 3 * DMODEL * DMODEL;
        round_perm_kernel<<<(n2 / 8 + 255) / 256, 256>>>(qkv_w, wq, n2);
        int n3 = DMODEL * DMODEL;
        round_perm_kernel<<<(n3 / 8 + 255) / 256, 256>>>(proj_w, wp, n3);
    }

    // QKV GEMM: [21824, 2304]
    {
        cudaFuncSetAttribute(gemm_v3<3 * DMODEL>,
                             cudaFuncAttributeMaxDynamicSharedMemorySize, GEMM_SMEM);
        dim3 grid((3 * DMODEL) / B_ROWS, (MTOK + A_ROWS - 1) / A_ROWS);  // (9, 171)
        gemm_v3<3 * DMODEL><<<grid, 256, GEMM_SMEM>>>(xr, wq, qkv_b, qkv, MTOK);
    }
    // attention
    {
        const int smem = (2 * 64 * KS_STRIDE + 64 * VS_STRIDE) * 4;
        cudaFuncSetAttribute(attn_kernel, cudaFuncAttributeMaxDynamicSharedMemorySize, smem);
        dim3 grid((TOTAL_N + 63) / 64, NHEADS, BATCH);
        attn_kernel<<<grid, 128, smem>>>();
    }
    // proj GEMM: [21824, 768]
    {
        cudaFuncSetAttribute(gemm_v3<DMODEL>,
                             cudaFuncAttributeMaxDynamicSharedMemorySize, GEMM_SMEM);
        dim3 grid(DMODEL / B_ROWS, (MTOK + A_ROWS - 1) / A_ROWS);  // (3, 171)
        gemm_v3<DMODEL><<<grid, 256, GEMM_SMEM>>>(att, wp, proj_b, out, MTOK);
    }
}

// round 10
// speedup vs baseline: 1.1827x; 1.1827x over previous
#include <cuda_runtime.h>
#include <cstdint>

// Problem constants
#define TOTAL_N 341
#define BATCH   64
#define DMODEL  768
#define NHEADS  12
#define HDIM    64
#define MTOK    (BATCH * TOTAL_N)   // 21824

// Scratch (device globals: allocation-free)
__device__ __align__(1024) float g_qkv [(size_t)MTOK * 3 * DMODEL];   // [M, 2304]
__device__ __align__(1024) float g_att [(size_t)MTOK * DMODEL];       // [M, 768]
__device__ __align__(1024) float g_xr  [(size_t)MTOK * DMODEL];       // RNA-rounded x
__device__ __align__(1024) float g_wqkv[(size_t)3 * DMODEL * DMODEL]; // RNA-rounded qkv_w
__device__ __align__(1024) float g_wproj[(size_t)DMODEL * DMODEL];    // RNA-rounded proj_w

// ---------------------------------------------------------------------------
// helpers
// ---------------------------------------------------------------------------
__device__ __forceinline__ float to_tf32(float x) {
    uint32_t y;
    asm("cvt.rna.tf32.f32 %0, %1;" : "=r"(y) : "f"(x));
    return __uint_as_float(y);
}

__device__ __forceinline__ uint32_t fau(float x) { return __float_as_uint(x); }

__device__ __forceinline__ void mma_tf32(float* c, const uint32_t* a, uint32_t b0, uint32_t b1) {
    asm volatile(
        "mma.sync.aligned.m16n8k8.row.col.f32.tf32.tf32.f32 "
        "{%0,%1,%2,%3}, {%4,%5,%6,%7}, {%8,%9}, {%0,%1,%2,%3};\n"
        : "+f"(c[0]), "+f"(c[1]), "+f"(c[2]), "+f"(c[3])
        : "r"(a[0]), "r"(a[1]), "r"(a[2]), "r"(a[3]), "r"(b0), "r"(b1));
}

__device__ __forceinline__ int limit_of(int q) {
    if (q == 0)  return 341;
    if (q < 5)   return 5;
    if (q < 21)  return 21;
    if (q < 85)  return 85;
    return 341;
}

__device__ __forceinline__ void cp16(uint32_t dst, const float* src, int sz) {
    asm volatile("cp.async.cg.shared.global [%0], [%1], 16, %2;\n"
                 :: "r"(dst), "l"(src), "r"(sz));
}

__device__ __forceinline__ uint32_t smem_u32(const void* p) {
    return (uint32_t)__cvta_generic_to_shared(p);
}

// ---------------------------------------------------------------------------
// RNA pre-round kernel (fp32 -> tf32-valued fp32)
// ---------------------------------------------------------------------------
__global__ __launch_bounds__(256) void round_kernel(const float* __restrict__ s,
                                                    float* __restrict__ d, int n) {
    int i = (blockIdx.x * blockDim.x + threadIdx.x) * 4;
    if (i < n) {
        float4 v = *(const float4*)(s + i);
        v.x = to_tf32(v.x); v.y = to_tf32(v.y); v.z = to_tf32(v.z); v.w = to_tf32(v.w);
        *(float4*)(d + i) = v;
    }
}

// ---------------------------------------------------------------------------
// mma.sync tf32 GEMM v4: C[M,NG] = A[M,768] @ W[NG,768]^T + bias[NG]
// CTA tile 128(M) x 256(N) x 32(K). 8 warps (2 x 4), warp tile 64x64.
// 3-stage cp.async pipeline (R7 barrier structure) + REGISTER DOUBLE-BUFFERED
// fragments across ks-steps: LDS for ks+1 overlaps the 32 MMAs of ks.
// smem row stride 36 floats: scalar LDS pattern (4g+t) mod 32 conflict-free.
// ---------------------------------------------------------------------------
#define TK     32
#define RS     36                                  // row stride in floats
#define A_ROWS 128
#define B_ROWS 256
#define STG_FL ((A_ROWS + B_ROWS) * RS)            // floats per stage: 13824
#define STG_B  (STG_FL * 4)                        // 55296 bytes
#define NSTG   3
#define GEMM_SMEM (NSTG * STG_B)                   // 165888 bytes

template <int NG>
__global__ __launch_bounds__(256, 1) void gemm_v4(const float* __restrict__ A,
                                                  const float* __restrict__ W,
                                                  const float* __restrict__ bias,
                                                  float* __restrict__ C, int M) {
    extern __shared__ float sm[];

    const int tid  = threadIdx.x;
    const int lane = tid & 31;
    const int warp = tid >> 5;
    const int g    = lane >> 2;   // 0..7
    const int t    = lane & 3;    // 0..3
    const int wm   = warp >> 2;   // 0..1  (M half)
    const int wn   = warp & 3;    // 0..3  (N quarter)
    const int bm   = blockIdx.y * A_ROWS;
    const int bn   = blockIdx.x * B_ROWS;

    const uint32_t smb = smem_u32(sm);

    // issue one stage of cp.async: A tile 128x32, B tile 256x32
    auto issue = [&](int kb, int s) {
        uint32_t base = smb + s * STG_B;
#pragma unroll
        for (int i = 0; i < 4; i++) {
            int idx = tid + i * 256;
            int row = idx >> 3, c = idx & 7;
            int gr = bm + row;
            int ok = gr < M;
            const float* src = A + (size_t)(ok ? gr : 0) * DMODEL + kb * TK + c * 4;
            cp16(base + (row * RS + c * 4) * 4, src, ok ? 16 : 0);
        }
        uint32_t bbase = base + A_ROWS * RS * 4;
#pragma unroll
        for (int i = 0; i < 8; i++) {
            int idx = tid + i * 256;
            int row = idx >> 3, c = idx & 7;
            const float* src = W + (size_t)(bn + row) * DMODEL + kb * TK + c * 4;
            cp16(bbase + (row * RS + c * 4) * 4, src, 16);
        }
    };

    float acc[4][8][4];
#pragma unroll
    for (int mi = 0; mi < 4; mi++)
#pragma unroll
        for (int ni = 0; ni < 8; ni++)
#pragma unroll
            for (int j = 0; j < 4; j++) acc[mi][ni][j] = 0.f;

    const int KT = DMODEL / TK;  // 24

    issue(0, 0);
    asm volatile("cp.async.commit_group;" ::: "memory");
    issue(1, 1);
    asm volatile("cp.async.commit_group;" ::: "memory");

    // fragment double buffers (2 x (A:16 + B:16) regs)
    uint32_t afb[2][4][4];
    uint32_t bfb[2][8][2];

    for (int kb = 0; kb < KT; kb++) {
        asm volatile("cp.async.wait_group 1;" ::: "memory");
        __syncthreads();

        const int s = kb % NSTG;
        const float* As = sm + s * STG_FL;
        const float* Bs = As + A_ROWS * RS;
        const float* Ap = As + (wm * 64 + g) * RS + t;   // + mi*16*RS + ks*8
        const float* Bp = Bs + (wn * 64 + g) * RS + t;   // + ni*8*RS  + ks*8

        // preload ks=0 fragments
#pragma unroll
        for (int mi = 0; mi < 4; mi++) {
            const float* p = Ap + mi * 16 * RS;
            afb[0][mi][0] = fau(p[0]);
            afb[0][mi][1] = fau(p[8 * RS]);
            afb[0][mi][2] = fau(p[4]);
            afb[0][mi][3] = fau(p[8 * RS + 4]);
        }
#pragma unroll
        for (int ni = 0; ni < 8; ni++) {
            const float* p = Bp + ni * 8 * RS;
            bfb[0][ni][0] = fau(p[0]);
            bfb[0][ni][1] = fau(p[4]);
        }

#pragma unroll
        for (int ks = 0; ks < 4; ks++) {
            const int cur = ks & 1, nxt = cur ^ 1;
            if (ks < 3) {
                const int k1 = (ks + 1) * 8;
#pragma unroll
                for (int mi = 0; mi < 4; mi++) {
                    const float* p = Ap + mi * 16 * RS + k1;
                    afb[nxt][mi][0] = fau(p[0]);
                    afb[nxt][mi][1] = fau(p[8 * RS]);
                    afb[nxt][mi][2] = fau(p[4]);
                    afb[nxt][mi][3] = fau(p[8 * RS + 4]);
                }
#pragma unroll
                for (int ni = 0; ni < 8; ni++) {
                    const float* p = Bp + ni * 8 * RS + k1;
                    bfb[nxt][ni][0] = fau(p[0]);
                    bfb[nxt][ni][1] = fau(p[4]);
                }
            }
#pragma unroll
            for (int ni = 0; ni < 8; ni++) {
#pragma unroll
                for (int mi = 0; mi < 4; mi++)
                    mma_tf32(acc[mi][ni], afb[cur][mi], bfb[cur][ni][0], bfb[cur][ni][1]);
            }
        }
        __syncthreads();

        if (kb + 2 < KT) issue(kb + 2, (kb + 2) % NSTG);
        asm volatile("cp.async.commit_group;" ::: "memory");
    }

    // epilogue: + bias, store
#pragma unroll
    for (int mi = 0; mi < 4; mi++) {
        int r0 = bm + wm * 64 + mi * 16 + g;
        int r1 = r0 + 8;
#pragma unroll
        for (int ni = 0; ni < 8; ni++) {
            int col = bn + wn * 64 + ni * 8 + 2 * t;
            float b0 = bias[col], b1 = bias[col + 1];
            if (r0 < M) {
                float2 v = make_float2(acc[mi][ni][0] + b0, acc[mi][ni][1] + b1);
                *(float2*)(C + (size_t)r0 * NG + col) = v;
            }
            if (r1 < M) {
                float2 v = make_float2(acc[mi][ni][2] + b0, acc[mi][ni][3] + b1);
                *(float2*)(C + (size_t)r1 * NG + col) = v;
            }
        }
    }
}

// ---------------------------------------------------------------------------
// Fused flash attention: one CTA = (q-tile of 64 rows, head, batch)
// 4 warps x 16 q-rows. tf32 mma for S=Q K^T and O += P V. (R7 known-good)
// ---------------------------------------------------------------------------
#define KS_STRIDE 68
#define VS_STRIDE 72

__global__ __launch_bounds__(128) void attn_kernel() {
    extern __shared__ float sm[];
    float* Ks = sm;
    float* Ps = sm + 64 * KS_STRIDE;
    float* Vs = sm + 2 * 64 * KS_STRIDE;

    const int tid  = threadIdx.x;
    const int lane = tid & 31;
    const int warp = tid >> 5;
    const int g    = lane >> 2;
    const int t    = lane & 3;

    const int q0 = blockIdx.x * 64;
    const int h  = blockIdx.y;
    const int b  = blockIdx.z;
    const size_t rowbase = (size_t)b * TOTAL_N;
    const int hoff = h * HDIM;

#pragma unroll
    for (int i = 0; i < 8; i++) {
        int idx = tid + i * 128;
        int row = idx >> 4;
        int c4  = (idx & 15) << 2;
        float4 v = make_float4(0.f, 0.f, 0.f, 0.f);
        int qi = q0 + row;
        if (qi < TOTAL_N) v = *(const float4*)(g_qkv + (rowbase + qi) * 2304 + hoff + c4);
        v.x = to_tf32(v.x); v.y = to_tf32(v.y); v.z = to_tf32(v.z); v.w = to_tf32(v.w);
        *(float4*)(Ps + row * KS_STRIDE + c4) = v;
    }
    __syncthreads();

    const int prow = warp * 16 + g;
    uint32_t qf[8][4];
#pragma unroll
    for (int d8 = 0; d8 < 8; d8++) {
        const float* p = Ps + prow * KS_STRIDE + d8 * 8 + t;
        qf[d8][0] = fau(p[0]);
        qf[d8][1] = fau(p[8 * KS_STRIDE]);
        qf[d8][2] = fau(p[4]);
        qf[d8][3] = fau(p[8 * KS_STRIDE + 4]);
    }
    __syncthreads();

    float o[8][4];
#pragma unroll
    for (int d8 = 0; d8 < 8; d8++)
#pragma unroll
        for (int j = 0; j < 4; j++) o[d8][j] = 0.f;

    float m0 = -1e30f, m1 = -1e30f, l0 = 0.f, l1 = 0.f;
    const int lim0 = limit_of(q0 + prow);
    const int lim1 = limit_of(q0 + prow + 8);

    for (int kt = 0; kt < 6; kt++) {
        int key0 = kt * 64;
#pragma unroll
        for (int i = 0; i < 8; i++) {
            int idx = tid + i * 128;
            int row = idx >> 4;
            int c4  = (idx & 15) << 2;
            float4 kv = make_float4(0.f, 0.f, 0.f, 0.f);
            float4 vv = make_float4(0.f, 0.f, 0.f, 0.f);
            int key = key0 + row;
            if (key < TOTAL_N) {
                const float* base = g_qkv + (rowbase + key) * 2304 + hoff;
                kv = *(const float4*)(base + DMODEL + c4);
                vv = *(const float4*)(base + 2 * DMODEL + c4);
            }
            kv.x = to_tf32(kv.x); kv.y = to_tf32(kv.y); kv.z = to_tf32(kv.z); kv.w = to_tf32(kv.w);
            vv.x = to_tf32(vv.x); vv.y = to_tf32(vv.y); vv.z = to_tf32(vv.z); vv.w = to_tf32(vv.w);
            *(float4*)(Ks + row * KS_STRIDE + c4) = kv;
            *(float4*)(Vs + row * VS_STRIDE + c4) = vv;
        }
        __syncthreads();

        float s[8][4];
#pragma unroll
        for (int ni = 0; ni < 8; ni++)
#pragma unroll
            for (int j = 0; j < 4; j++) s[ni][j] = 0.f;

#pragma unroll
        for (int d8 = 0; d8 < 8; d8++) {
#pragma unroll
            for (int ni = 0; ni < 8; ni++) {
                const float* p = Ks + (ni * 8 + g) * KS_STRIDE + d8 * 8 + t;
                mma_tf32(s[ni], qf[d8], fau(p[0]), fau(p[4]));
            }
        }

        float mx0 = -1e30f, mx1 = -1e30f;
#pragma unroll
        for (int ni = 0; ni < 8; ni++) {
            int col = key0 + ni * 8 + 2 * t;
            s[ni][0] = (col     < lim0) ? s[ni][0] * 0.125f : -1e30f;
            s[ni][1] = (col + 1 < lim0) ? s[ni][1] * 0.125f : -1e30f;
            s[ni][2] = (col     < lim1) ? s[ni][2] * 0.125f : -1e30f;
            s[ni][3] = (col + 1 < lim1) ? s[ni][3] * 0.125f : -1e30f;
            mx0 = fmaxf(mx0, fmaxf(s[ni][0], s[ni][1]));
            mx1 = fmaxf(mx1, fmaxf(s[ni][2], s[ni][3]));
        }
        mx0 = fmaxf(mx0, __shfl_xor_sync(0xffffffffu, mx0, 1));
        mx0 = fmaxf(mx0, __shfl_xor_sync(0xffffffffu, mx0, 2));
        mx1 = fmaxf(mx1, __shfl_xor_sync(0xffffffffu, mx1, 1));
        mx1 = fmaxf(mx1, __shfl_xor_sync(0xffffffffu, mx1, 2));

        float mn0 = fmaxf(m0, mx0);
        float mn1 = fmaxf(m1, mx1);
        float sc0 = __expf(m0 - mn0);
        float sc1 = __expf(m1 - mn1);
        m0 = mn0; m1 = mn1;

        float rs0 = 0.f, rs1 = 0.f;
#pragma unroll
        for (int ni = 0; ni < 8; ni++) {
            float p0 = __expf(s[ni][0] - mn0);
            float p1 = __expf(s[ni][1] - mn0);
            float p2 = __expf(s[ni][2] - mn1);
            float p3 = __expf(s[ni][3] - mn1);
            rs0 += p0 + p1;
            rs1 += p2 + p3;
            *(float2*)(Ps + prow * KS_STRIDE + ni * 8 + 2 * t) =
                make_float2(to_tf32(p0), to_tf32(p1));
            *(float2*)(Ps + (prow + 8) * KS_STRIDE + ni * 8 + 2 * t) =
                make_float2(to_tf32(p2), to_tf32(p3));
        }
        rs0 += __shfl_xor_sync(0xffffffffu, rs0, 1);
        rs0 += __shfl_xor_sync(0xffffffffu, rs0, 2);
        rs1 += __shfl_xor_sync(0xffffffffu, rs1, 1);
        rs1 += __shfl_xor_sync(0xffffffffu, rs1, 2);
        l0 = l0 * sc0 + rs0;
        l1 = l1 * sc1 + rs1;

#pragma unroll
        for (int d8 = 0; d8 < 8; d8++) {
            o[d8][0] *= sc0; o[d8][1] *= sc0;
            o[d8][2] *= sc1; o[d8][3] *= sc1;
        }
        __syncwarp();

#pragma unroll
        for (int kk = 0; kk < 8; kk++) {
            uint32_t af[4];
            const float* pp = Ps + prow * KS_STRIDE + kk * 8 + t;
            af[0] = fau(pp[0]);
            af[1] = fau(pp[8 * KS_STRIDE]);
            af[2] = fau(pp[4]);
            af[3] = fau(pp[8 * KS_STRIDE + 4]);
#pragma unroll
            for (int d8 = 0; d8 < 8; d8++) {
                const float* pv = Vs + (kk * 8 + t) * VS_STRIDE + d8 * 8 + g;
                mma_tf32(o[d8], af, fau(pv[0]), fau(pv[4 * VS_STRIDE]));
            }
        }
        __syncthreads();
    }

    float il0 = 1.f / l0;
    float il1 = 1.f / l1;
    int r0 = q0 + prow;
    int r1 = r0 + 8;
#pragma unroll
    for (int d8 = 0; d8 < 8; d8++) {
        int col = hoff + d8 * 8 + 2 * t;
        if (r0 < TOTAL_N)
            *(float2*)(g_att + (rowbase + r0) * DMODEL + col) =
                make_float2(to_tf32(o[d8][0] * il0), to_tf32(o[d8][1] * il0));
        if (r1 < TOTAL_N)
            *(float2*)(g_att + (rowbase + r1) * DMODEL + col) =
                make_float2(to_tf32(o[d8][2] * il1), to_tf32(o[d8][3] * il1));
    }
}

// ---------------------------------------------------------------------------
// launch
// ---------------------------------------------------------------------------
extern "C" void kernel_launch(void* const* d_in, const int* in_sizes, int n_in,
                              void* d_out, int out_size) {
    (void)in_sizes; (void)n_in; (void)out_size;
    const float* x      = (const float*)d_in[0];
    const float* qkv_w  = (const float*)d_in[1];
    const float* qkv_b  = (const float*)d_in[2];
    const float* proj_w = (const float*)d_in[3];
    const float* proj_b = (const float*)d_in[4];
    float* out = (float*)d_out;

    float *xr, *wq, *wp, *qkv, *att;
    cudaGetSymbolAddress((void**)&xr,  g_xr);
    cudaGetSymbolAddress((void**)&wq,  g_wqkv);
    cudaGetSymbolAddress((void**)&wp,  g_wproj);
    cudaGetSymbolAddress((void**)&qkv, g_qkv);
    cudaGetSymbolAddress((void**)&att, g_att);

    // RNA pre-round inputs (so cp.async-staged bits are exact tf32 values)
    {
        int n1 = MTOK * DMODEL;
        round_kernel<<<(n1 / 4 + 255) / 256, 256>>>(x, xr, n1);
        int n2 = 3 * DMODEL * DMODEL;
        round_kernel<<<(n2 / 4 + 255) / 256, 256>>>(qkv_w, wq, n2);
        int n3 = DMODEL * DMODEL;
        round_kernel<<<(n3 / 4 + 255) / 256, 256>>>(proj_w, wp, n3);
    }

    // QKV GEMM: [21824, 2304]
    {
        cudaFuncSetAttribute(gemm_v4<3 * DMODEL>,
                             cudaFuncAttributeMaxDynamicSharedMemorySize, GEMM_SMEM);
        dim3 grid((3 * DMODEL) / B_ROWS, (MTOK + A_ROWS - 1) / A_ROWS);  // (9, 171)
        gemm_v4<3 * DMODEL><<<grid, 256, GEMM_SMEM>>>(xr, wq, qkv_b, qkv, MTOK);
    }
    // attention
    {
        const int smem = (2 * 64 * KS_STRIDE + 64 * VS_STRIDE) * 4;
        cudaFuncSetAttribute(attn_kernel, cudaFuncAttributeMaxDynamicSharedMemorySize, smem);
        dim3 grid((TOTAL_N + 63) / 64, NHEADS, BATCH);
        attn_kernel<<<grid, 128, smem>>>();
    }
    // proj GEMM: [21824, 768]
    {
        cudaFuncSetAttribute(gemm_v4<DMODEL>,
                             cudaFuncAttributeMaxDynamicSharedMemorySize, GEMM_SMEM);
        dim3 grid(DMODEL / B_ROWS, (MTOK + A_ROWS - 1) / A_ROWS);  // (3, 171)
        gemm_v4<DMODEL><<<grid, 256, GEMM_SMEM>>>(att, wp, proj_b, out, MTOK);
    }
}